// round 4
// baseline (speedup 1.0000x reference)
#include <cuda_runtime.h>
#include <math.h>

// Problem dims
#define Bsz  128
#define Nn   1024
#define Dd   256
#define Gg   64
#define GSZc 3
#define RELD 16
#define KDc  64
#define PDc  64
#define NFc  64
#define Qq   (Gg * GSZc)          // 192

// ---------------- scratch (static device globals; no allocation) ------------
__device__ float g_pe[Nn * KDc];                     // 65536   PE table
__device__ float g_fsym[NFc * GSZc * GSZc * RELD];   // 9216    symmetrized filters
__device__ float g_wt[Dd * 2 * RELD * PDc];          // 256x2048 Wq|Wk transposed
__device__ float g_k[Bsz * Nn * KDc];                // 8.4M    keys
__device__ float g_sc[Bsz * Qq * Nn];                // 25.2M   logits/scores
__device__ float g_gobj[Bsz * Qq * Dd];              // 6.3M    attended objects
__device__ float g_zz[(long)Bsz * Qq * 2048];        // 50.3M   zq|zk

// ---------------- small precompute kernels ----------------------------------

// Sinusoidal PE table. Angle rounded like the f32 reference; sin/cos in double
// so fast-math can't substitute an inaccurate __sinf at large arguments.
__global__ void pe_kernel() {
    int idx = blockIdx.x * blockDim.x + threadIdx.x;
    if (idx >= Nn * KDc) return;
    int n = idx >> 6, j = idx & 63;
    float e = (float)(j & ~1) / 64.0f;
    float denom = powf(10000.0f, e);
    float angle = (float)n / denom;
    double a = (double)angle;
    g_pe[idx] = (j & 1) ? (float)cos(a) : (float)sin(a);
}

// Fsym[f,n,m,r] = (1/6) sum over all 6 permutations sigma of F[f,sigma(n),sigma(m),r]
__global__ void fsym_kernel(const float* __restrict__ filters) {
    int idx = blockIdx.x * blockDim.x + threadIdx.x;
    if (idx >= NFc * 144) return;
    int f = idx / 144, rem = idx % 144;
    int n = rem / 48, m = (rem / 16) % 3, r = rem & 15;
    const int P[6][3] = {{0,1,2},{0,2,1},{1,0,2},{1,2,0},{2,0,1},{2,1,0}};
    float s = 0.f;
#pragma unroll
    for (int p = 0; p < 6; p++)
        s += filters[f * 144 + P[p][n] * 48 + P[p][m] * 16 + r];
    g_fsym[idx] = s * (1.0f / 6.0f);
}

// W'[d][c] with c = r*64+p (Wq for c<1024, Wk for c>=1024); src Wq[r,d,p]
__global__ void wtrans_kernel(const float* __restrict__ Wq,
                              const float* __restrict__ Wk) {
    int idx = blockIdx.x * blockDim.x + threadIdx.x;
    if (idx >= Dd * 2048) return;
    int d = idx >> 11, c = idx & 2047;
    const float* W = (c < 1024) ? Wq : Wk;
    int cc = c & 1023;
    int r = cc >> 6, p = cc & 63;
    g_wt[idx] = W[(r << 14) + (d << 6) + p];   // r*16384 + d*64 + p
}

// ---------------- tiled SGEMM (row-major A,B,C) ------------------------------
// BM=BN=64, BK=16, 256 threads, 4x4 microtile. M,N %64==0, K %16==0 (holds here).
__global__ __launch_bounds__(256)
void gemm_nn(const float* __restrict__ A, const float* __restrict__ B,
             float* __restrict__ C, int M, int N, int K,
             long sA, long sB, long sC, float alpha, int add_pe) {
    A += (long)blockIdx.z * sA;
    B += (long)blockIdx.z * sB;
    C += (long)blockIdx.z * sC;
    const int m0 = blockIdx.y * 64;
    const int n0 = blockIdx.x * 64;
    __shared__ float As[16][64];
    __shared__ float Bs[16][64];
    const int t = threadIdx.x;
    const int a_row = t >> 2, a_kc = (t & 3) << 2;
    const int b_k = t >> 4, b_c = (t & 15) << 2;
    const int tr = (t >> 4) << 2, tc = (t & 15) << 2;
    float acc[4][4] = {};
    for (int k0 = 0; k0 < K; k0 += 16) {
        float4 av = *(const float4*)&A[(long)(m0 + a_row) * K + k0 + a_kc];
        As[a_kc + 0][a_row] = av.x;
        As[a_kc + 1][a_row] = av.y;
        As[a_kc + 2][a_row] = av.z;
        As[a_kc + 3][a_row] = av.w;
        *(float4*)&Bs[b_k][b_c] = *(const float4*)&B[(long)(k0 + b_k) * N + n0 + b_c];
        __syncthreads();
#pragma unroll
        for (int kk = 0; kk < 16; kk++) {
            float4 a4 = *(const float4*)&As[kk][tr];
            float4 b4 = *(const float4*)&Bs[kk][tc];
            float ar[4] = {a4.x, a4.y, a4.z, a4.w};
            float br[4] = {b4.x, b4.y, b4.z, b4.w};
#pragma unroll
            for (int i = 0; i < 4; i++)
#pragma unroll
                for (int j = 0; j < 4; j++) acc[i][j] += ar[i] * br[j];
        }
        __syncthreads();
    }
#pragma unroll
    for (int i = 0; i < 4; i++) {
        int row = m0 + tr + i;
        long cb = (long)row * N + n0 + tc;
        float4 o;
        o.x = acc[i][0] * alpha; o.y = acc[i][1] * alpha;
        o.z = acc[i][2] * alpha; o.w = acc[i][3] * alpha;
        if (add_pe) {
            const float* pe = &g_pe[(row & (Nn - 1)) * 64 + n0 + tc];
            o.x += pe[0]; o.y += pe[1]; o.z += pe[2]; o.w += pe[3];
        }
        *(float4*)&C[cb] = o;
    }
}

// C = alpha * A @ B^T, B is (N x K) row-major
__global__ __launch_bounds__(256)
void gemm_nt(const float* __restrict__ A, const float* __restrict__ B,
             float* __restrict__ C, int M, int N, int K,
             long sA, long sB, long sC, float alpha) {
    A += (long)blockIdx.z * sA;
    B += (long)blockIdx.z * sB;
    C += (long)blockIdx.z * sC;
    const int m0 = blockIdx.y * 64;
    const int n0 = blockIdx.x * 64;
    __shared__ float As[16][64];
    __shared__ float Bs[16][64];
    const int t = threadIdx.x;
    const int l_row = t >> 2, l_kc = (t & 3) << 2;
    const int tr = (t >> 4) << 2, tc = (t & 15) << 2;
    float acc[4][4] = {};
    for (int k0 = 0; k0 < K; k0 += 16) {
        float4 av = *(const float4*)&A[(long)(m0 + l_row) * K + k0 + l_kc];
        As[l_kc + 0][l_row] = av.x;
        As[l_kc + 1][l_row] = av.y;
        As[l_kc + 2][l_row] = av.z;
        As[l_kc + 3][l_row] = av.w;
        float4 bv = *(const float4*)&B[(long)(n0 + l_row) * K + k0 + l_kc];
        Bs[l_kc + 0][l_row] = bv.x;
        Bs[l_kc + 1][l_row] = bv.y;
        Bs[l_kc + 2][l_row] = bv.z;
        Bs[l_kc + 3][l_row] = bv.w;
        __syncthreads();
#pragma unroll
        for (int kk = 0; kk < 16; kk++) {
            float4 a4 = *(const float4*)&As[kk][tr];
            float4 b4 = *(const float4*)&Bs[kk][tc];
            float ar[4] = {a4.x, a4.y, a4.z, a4.w};
            float br[4] = {b4.x, b4.y, b4.z, b4.w};
#pragma unroll
            for (int i = 0; i < 4; i++)
#pragma unroll
                for (int j = 0; j < 4; j++) acc[i][j] += ar[i] * br[j];
        }
        __syncthreads();
    }
#pragma unroll
    for (int i = 0; i < 4; i++) {
        long cb = (long)(m0 + tr + i) * N + n0 + tc;
        float4 o;
        o.x = acc[i][0] * alpha; o.y = acc[i][1] * alpha;
        o.z = acc[i][2] * alpha; o.w = acc[i][3] * alpha;
        *(float4*)&C[cb] = o;
    }
}

// ---------------- row softmax over 1024, in place ----------------------------
__global__ __launch_bounds__(256)
void softmax_kernel(float* __restrict__ data) {
    __shared__ float red_m[8], red_s[8];
    float* p = data + (long)blockIdx.x * 1024;
    int t = threadIdx.x;
    float4 v = ((float4*)p)[t];
    float m = fmaxf(fmaxf(v.x, v.y), fmaxf(v.z, v.w));
#pragma unroll
    for (int o = 16; o; o >>= 1) m = fmaxf(m, __shfl_xor_sync(0xffffffffu, m, o));
    if ((t & 31) == 0) red_m[t >> 5] = m;
    __syncthreads();
    float bm = red_m[0];
#pragma unroll
    for (int i = 1; i < 8; i++) bm = fmaxf(bm, red_m[i]);
    v.x = expf(v.x - bm); v.y = expf(v.y - bm);
    v.z = expf(v.z - bm); v.w = expf(v.w - bm);
    float s = v.x + v.y + v.z + v.w;
#pragma unroll
    for (int o = 16; o; o >>= 1) s += __shfl_xor_sync(0xffffffffu, s, o);
    if ((t & 31) == 0) red_s[t >> 5] = s;
    __syncthreads();
    float tot = red_s[0];
#pragma unroll
    for (int i = 1; i < 8; i++) tot += red_s[i];
    float inv = 1.0f / tot;
    v.x *= inv; v.y *= inv; v.z *= inv; v.w *= inv;
    ((float4*)p)[t] = v;
}

// ---------------- final: R[n,m,r] then contract with Fsym --------------------
// One block per (b,g). 288 threads = 9 warps; warp w handles (n,m)=(w/3,w%3).
// Lanes read consecutive p (conflict-free), shuffle-reduce -> Rs[144].
// Then 64 threads contract Rs with Fsym (broadcast smem reads, L1-hot Fsym).
__global__ __launch_bounds__(288)
void final_kernel(const float* __restrict__ zz, float* __restrict__ out) {
    __shared__ float s[3 * 2048];
    __shared__ float Rs[144];
    const int bg = blockIdx.x;                  // b*64+g
    const long base = (long)bg * 3 * 2048;      // row b*192+g*3 = 3*bg
    const int t = threadIdx.x;
    const float4* src = (const float4*)(zz + base);
    float4* dst = (float4*)s;
    for (int i = t; i < 1536; i += 288) dst[i] = src[i];
    __syncthreads();

    const int w = t >> 5, lane = t & 31;
    const int n = w / 3, m = w % 3;
    const float* za = s + n * 2048;             // zq row n
    const float* zb = s + m * 2048 + 1024;      // zk row m
#pragma unroll
    for (int r = 0; r < 16; r++) {
        float part = za[r * 64 + lane] * zb[r * 64 + lane]
                   + za[r * 64 + 32 + lane] * zb[r * 64 + 32 + lane];
#pragma unroll
        for (int o = 16; o; o >>= 1) part += __shfl_xor_sync(0xffffffffu, part, o);
        if (lane == 0) Rs[(n * 3 + m) * 16 + r] = part;
    }
    __syncthreads();

    if (t < 64) {
        const float* f = g_fsym + t * 144;
        float acc = 0.f;
#pragma unroll 16
        for (int i = 0; i < 144; i++) acc += Rs[i] * f[i];
        out[(long)bg * 64 + t] = acc;
    }
}

// ---------------- launch -----------------------------------------------------
extern "C" void kernel_launch(void* const* d_in, const int* in_sizes, int n_in,
                              void* d_out, int out_size) {
    (void)in_sizes; (void)n_in; (void)out_size;
    const float* x       = (const float*)d_in[0];   // (B,N,D)
    const float* filters = (const float*)d_in[1];   // (NF,3,3,16)
    const float* qe      = (const float*)d_in[2];   // (192,64)
    const float* wkmap   = (const float*)d_in[3];   // (256,64)
    const float* Wq      = (const float*)d_in[4];   // (16,256,64)
    const float* Wk      = (const float*)d_in[5];   // (16,256,64)
    float* out = (float*)d_out;                     // (B,G,NF) f32

    float *pk, *psc, *pg, *pzz, *pwt;
    cudaGetSymbolAddress((void**)&pk,  g_k);
    cudaGetSymbolAddress((void**)&psc, g_sc);
    cudaGetSymbolAddress((void**)&pg,  g_gobj);
    cudaGetSymbolAddress((void**)&pzz, g_zz);
    cudaGetSymbolAddress((void**)&pwt, g_wt);

    pe_kernel<<<(Nn * KDc + 255) / 256, 256>>>();
    fsym_kernel<<<(NFc * 144 + 255) / 256, 256>>>(filters);
    wtrans_kernel<<<(Dd * 2048 + 255) / 256, 256>>>(Wq, Wk);

    // k = x @ Wk_map + PE : (131072 x 64 x 256)
    {
        dim3 g(KDc / 64, (Bsz * Nn) / 64, 1);
        gemm_nn<<<g, 256>>>(x, wkmap, pk, Bsz * Nn, KDc, Dd, 0, 0, 0, 1.0f, 1);
    }
    // logits = beta * qe @ k[b]^T : batched (192 x 1024 x 64)
    {
        dim3 g(Nn / 64, Qq / 64, Bsz);
        gemm_nt<<<g, 256>>>(qe, pk, psc, Qq, Nn, KDc,
                            0, (long)Nn * KDc, (long)Qq * Nn, 0.125f);
    }
    softmax_kernel<<<Bsz * Qq, 256>>>(psc);
    // gobj = scores @ x : batched (192 x 256 x 1024)
    {
        dim3 g(Dd / 64, Qq / 64, Bsz);
        gemm_nn<<<g, 256>>>(psc, x, pg, Qq, Dd, Nn,
                            (long)Qq * Nn, (long)Nn * Dd, (long)Qq * Dd, 1.0f, 0);
    }
    // zz = gobj @ W' : (24576 x 2048 x 256)  [zq | zk]
    {
        dim3 g(2048 / 64, (Bsz * Qq) / 64, 1);
        gemm_nn<<<g, 256>>>(pg, pwt, pzz, Bsz * Qq, 2048, Dd, 0, 0, 0, 1.0f, 0);
    }
    final_kernel<<<Bsz * Gg, 288>>>(pzz, out);
}